// round 2
// baseline (speedup 1.0000x reference)
#include <cuda_runtime.h>
#include <cstdint>

// Problem constants
#define NROWS   524288          // NFRAG * FRAGLEN
#define DY      128
#define FRAG    1024
#define LEN     512
#define EPF     511             // edges per fragment
#define NEDGE   (FRAG * EPF)
#define DISTC   3.8f
#define NK      11              // max line-search trials (k = 0..10)
#define NITERS  10
#define CONV    1e-4f

// ---------------- device state (all reset / recomputed every launch) ----------------
__device__ float g_dx[NEDGE * 3];       // per-edge dx (first-3-coord diffs along chain)
__device__ float g_dA[NEDGE * 3];       // per-edge (lam3[n+1]-lam3[n]) @ A
__device__ float g_lam3[NROWS * 3];     // per-node lam3; holds r at init
__device__ float g_S3[NROWS * 3];       // sum_j a_eff_j * lam3_j  (applied lazily)
__device__ float g_partials[12 * FRAG]; // [k][frag] block partial sums (11 ct + cnorm)
__device__ float g_V[DY * 3];           // V[d][j] = Wu[d,j]+Wu[d,j+3]+Wu[d,j+6]
__device__ float g_A[9];                // A[j][i] = sum_d V[d][j] * Wp[i,d]
__device__ float g_alpha, g_aeff, g_Sa;
__device__ int   g_done;

// ---------------- precompute V (128x3), A (3x3); reset scalar state ----------------
__global__ void k_pre(const float* __restrict__ Wp, const float* __restrict__ Wu) {
    int d = threadIdx.x;  // 0..127
    if (d == 0) {
        g_alpha = 1.0f;
        g_aeff  = 0.0f;
        g_Sa    = 0.0f;
        g_done  = 0;
    }
    float v[3];
#pragma unroll
    for (int j = 0; j < 3; j++) {
        v[j] = Wu[d * 18 + j] + Wu[d * 18 + j + 3] + Wu[d * 18 + j + 6];
        g_V[d * 3 + j] = v[j];
    }
    __shared__ float red[128];
#pragma unroll
    for (int j = 0; j < 3; j++) {
#pragma unroll
        for (int i = 0; i < 3; i++) {
            red[d] = v[j] * Wp[i * DY + d];
            __syncthreads();
            for (int s = 64; s > 0; s >>= 1) {
                if (d < s) red[d] += red[d + s];
                __syncthreads();
            }
            if (d == 0) g_A[j * 3 + i] = red[0];
            __syncthreads();
        }
    }
}

// ---------------- r[n] = y[n] @ Wp[0:3]^T  (bias cancels in diffs); zero S3 ----------------
__global__ void k_r(const float* __restrict__ y, const float* __restrict__ Wp) {
    int gid  = blockIdx.x * blockDim.x + threadIdx.x;
    int row  = gid >> 5;
    int lane = gid & 31;
    if (row >= NROWS) return;
    const float4 v = reinterpret_cast<const float4*>(y + (size_t)row * DY)[lane];
    int d = lane * 4;
    float p[3];
#pragma unroll
    for (int i = 0; i < 3; i++) {
        const float* w = Wp + i * DY + d;
        p[i] = v.x * w[0] + v.y * w[1] + v.z * w[2] + v.w * w[3];
    }
#pragma unroll
    for (int i = 0; i < 3; i++)
#pragma unroll
        for (int o = 16; o > 0; o >>= 1)
            p[i] += __shfl_down_sync(0xffffffffu, p[i], o);
    if (lane == 0) {
#pragma unroll
        for (int i = 0; i < 3; i++) {
            g_lam3[row * 3 + i] = p[i];   // r stored in lam3 buffer for iteration 0
            g_S3[row * 3 + i]   = 0.0f;
        }
    }
}

// ---------------- per-iteration fused kernel: apply prev step, chain grad, line search ----------------
__global__ void __launch_bounds__(512) k_chain(int j) {
    const int f = blockIdx.x;
    const int t = threadIdx.x;           // node index within fragment (0..511)
    const int n = f * LEN + t;
    const int e = f * EPF + t;           // edge index (valid for t < 511)

    __shared__ float sr[LEN * 3];        // r (iter 0 only)
    __shared__ float ss[LEN * 3];        // s per edge
    __shared__ float wsum[16][12];

    float dx0 = 0.f, dx1 = 0.f, dx2 = 0.f;

    if (j == 0) {
        float r0 = g_lam3[n * 3 + 0], r1 = g_lam3[n * 3 + 1], r2 = g_lam3[n * 3 + 2];
        sr[t * 3 + 0] = r0; sr[t * 3 + 1] = r1; sr[t * 3 + 2] = r2;
        __syncthreads();
        if (t < EPF) {
            dx0 = sr[(t + 1) * 3 + 0] - r0;
            dx1 = sr[(t + 1) * 3 + 1] - r1;
            dx2 = sr[(t + 1) * 3 + 2] - r2;
            g_dx[e * 3 + 0] = dx0; g_dx[e * 3 + 1] = dx1; g_dx[e * 3 + 2] = dx2;
        }
    } else {
        const float ae = g_aeff;
        if (t < EPF) {
            dx0 = g_dx[e * 3 + 0] - ae * g_dA[e * 3 + 0];
            dx1 = g_dx[e * 3 + 1] - ae * g_dA[e * 3 + 1];
            dx2 = g_dx[e * 3 + 2] - ae * g_dA[e * 3 + 2];
            g_dx[e * 3 + 0] = dx0; g_dx[e * 3 + 1] = dx1; g_dx[e * 3 + 2] = dx2;
        }
        // lazily accumulate previous iteration's step into S3 (g_lam3 still holds lam3_{j-1})
#pragma unroll
        for (int i = 0; i < 3; i++)
            g_S3[n * 3 + i] += ae * g_lam3[n * 3 + i];
    }

    // s[e] = DIST * drn2^{-1.5} * c * dx ;  c = DIST/|dx| - 1
    float c2 = 0.f;
    if (t < EPF) {
        float q  = dx0 * dx0 + dx1 * dx1 + dx2 * dx2;
        float rs = rsqrtf(q);
        float c  = fmaf(DISTC, rs, -1.0f);
        float coef = DISTC * rs * rs * rs * c;
        ss[t * 3 + 0] = coef * dx0;
        ss[t * 3 + 1] = coef * dx1;
        ss[t * 3 + 2] = coef * dx2;
        c2 = c * c;
    }
    __syncthreads();

    // lam3[n] = s[n] - s[n-1], boundaries s[-1] = s[L-1] = 0
    float l0, l1, l2;
    if (t == 0)       { l0 = ss[0]; l1 = ss[1]; l2 = ss[2]; }
    else if (t < EPF) { l0 = ss[t*3+0] - ss[(t-1)*3+0];
                        l1 = ss[t*3+1] - ss[(t-1)*3+1];
                        l2 = ss[t*3+2] - ss[(t-1)*3+2]; }
    else              { l0 = -ss[(EPF-1)*3+0]; l1 = -ss[(EPF-1)*3+1]; l2 = -ss[(EPF-1)*3+2]; }
    g_lam3[n * 3 + 0] = l0; g_lam3[n * 3 + 1] = l1; g_lam3[n * 3 + 2] = l2;

    float acc[NK];
#pragma unroll
    for (int k = 0; k < NK; k++) acc[k] = 0.f;

    if (t < EPF) {
        // lam3[t+1]
        float m0, m1, m2;
        if (t + 1 < EPF) { m0 = ss[(t+1)*3+0] - ss[t*3+0];
                           m1 = ss[(t+1)*3+1] - ss[t*3+1];
                           m2 = ss[(t+1)*3+2] - ss[t*3+2]; }
        else             { m0 = -ss[(EPF-1)*3+0]; m1 = -ss[(EPF-1)*3+1]; m2 = -ss[(EPF-1)*3+2]; }
        float d0 = m0 - l0, d1 = m1 - l1, d2 = m2 - l2;
        // dA = dlam @ A   (dA_i = sum_j dlam_j * A[j*3+i])
        float a0v = d0 * g_A[0] + d1 * g_A[3] + d2 * g_A[6];
        float a1v = d0 * g_A[1] + d1 * g_A[4] + d2 * g_A[7];
        float a2v = d0 * g_A[2] + d1 * g_A[5] + d2 * g_A[8];
        g_dA[e * 3 + 0] = a0v; g_dA[e * 3 + 1] = a1v; g_dA[e * 3 + 2] = a2v;

        // line search: ct(alpha/2^k) for k = 0..10
        float a = g_alpha;
#pragma unroll
        for (int k = 0; k < NK; k++) {
            float v0 = fmaf(-a, a0v, dx0);
            float v1 = fmaf(-a, a1v, dx1);
            float v2 = fmaf(-a, a2v, dx2);
            float q  = v0 * v0 + v1 * v1 + v2 * v2;
            float term = fmaf(DISTC, rsqrtf(q), -1.0f);
            acc[k] = term * term;
            a *= 0.5f;
        }
    }

    // deterministic block reduction of 12 values
    float vals[12];
#pragma unroll
    for (int k = 0; k < NK; k++) vals[k] = acc[k];
    vals[11] = c2;
#pragma unroll
    for (int k = 0; k < 12; k++)
#pragma unroll
        for (int o = 16; o > 0; o >>= 1)
            vals[k] += __shfl_down_sync(0xffffffffu, vals[k], o);
    int lane = t & 31, w = t >> 5;
    if (lane == 0)
#pragma unroll
        for (int k = 0; k < 12; k++) wsum[w][k] = vals[k];
    __syncthreads();
    if (t < 12) {
        float s = 0.f;
#pragma unroll
        for (int ww = 0; ww < 16; ww++) s += wsum[ww][t];
        g_partials[t * FRAG + f] = s;
    }
}

// ---------------- deterministic global reduce + line-search selection ----------------
__global__ void __launch_bounds__(1024) k_select() {
    int t = threadIdx.x, lane = t & 31, w = t >> 5;
    __shared__ float ws[32];
    __shared__ float tot[12];
    for (int k = 0; k < 12; k++) {
        float v = g_partials[k * FRAG + t];
#pragma unroll
        for (int o = 16; o > 0; o >>= 1) v += __shfl_down_sync(0xffffffffu, v, o);
        if (lane == 0) ws[w] = v;
        __syncthreads();
        if (w == 0) {
            float u = ws[lane];
#pragma unroll
            for (int o = 16; o > 0; o >>= 1) u += __shfl_down_sync(0xffffffffu, u, o);
            if (lane == 0) tot[k] = u;
        }
        __syncthreads();
    }
    if (t == 0) {
        float cn = tot[11];
        float a0 = g_alpha;
        int kf = -1;
#pragma unroll
        for (int k = 0; k < NK; k++)
            if (kf < 0 && tot[k] < cn) kf = k;
        float af, ctry;
        int ls;
        if (kf >= 0) { af = ldexpf(a0, -kf); ls = kf; ctry = tot[kf]; }
        else         { af = ldexpf(a0, -11); ls = 11; ctry = tot[10]; }
        if (ls == 0 && ctry > CONV) af *= 1.5f;
        int dn = g_done;
        float ae = dn ? 0.0f : af;
        if (!dn) g_alpha = af;
        if (ctry < CONV) g_done = 1;
        g_aeff = ae;
        g_Sa  += ae;
    }
}

// ---------------- y_out = y0 - (S3 + a_last*lam3) @ V^T - Sa * b_u ----------------
__global__ void k_final(const float* __restrict__ y, const float* __restrict__ bu,
                        float* __restrict__ out) {
    int gid  = blockIdx.x * blockDim.x + threadIdx.x;
    int row  = gid >> 5;
    int lane = gid & 31;
    if (row >= NROWS) return;
    const float ae = g_aeff, Sa = g_Sa;
    float s0 = g_S3[row * 3 + 0] + ae * g_lam3[row * 3 + 0];
    float s1 = g_S3[row * 3 + 1] + ae * g_lam3[row * 3 + 1];
    float s2 = g_S3[row * 3 + 2] + ae * g_lam3[row * 3 + 2];
    int d = lane * 4;
    float4 yv = reinterpret_cast<const float4*>(y + (size_t)row * DY)[lane];
    float4 bv = reinterpret_cast<const float4*>(bu)[lane];
    float4 o;
    o.x = yv.x - (s0 * g_V[(d+0)*3+0] + s1 * g_V[(d+0)*3+1] + s2 * g_V[(d+0)*3+2]) - Sa * bv.x;
    o.y = yv.y - (s0 * g_V[(d+1)*3+0] + s1 * g_V[(d+1)*3+1] + s2 * g_V[(d+1)*3+2]) - Sa * bv.y;
    o.z = yv.z - (s0 * g_V[(d+2)*3+0] + s1 * g_V[(d+2)*3+1] + s2 * g_V[(d+2)*3+2]) - Sa * bv.z;
    o.w = yv.w - (s0 * g_V[(d+3)*3+0] + s1 * g_V[(d+3)*3+1] + s2 * g_V[(d+3)*3+2]) - Sa * bv.w;
    reinterpret_cast<float4*>(out + (size_t)row * DY)[lane] = o;
}

extern "C" void kernel_launch(void* const* d_in, const int* in_sizes, int n_in,
                              void* d_out, int out_size) {
    const float* y  = (const float*)d_in[0];
    const float* Wp = (const float*)d_in[1];
    // d_in[2] = b_p (cancels in edge diffs), d_in[5]=batch, d_in[6]=fragid (baked in)
    const float* Wu = (const float*)d_in[3];
    const float* bu = (const float*)d_in[4];
    float* out = (float*)d_out;

    k_pre<<<1, 128>>>(Wp, Wu);
    k_r<<<NROWS / 8, 256>>>(y, Wp);
    for (int j = 0; j < NITERS; j++) {
        k_chain<<<FRAG, 512>>>(j);
        k_select<<<1, 1024>>>();
    }
    k_final<<<NROWS / 8, 256>>>(y, bu, out);
}

// round 4
// speedup vs baseline: 1.0788x; 1.0788x over previous
#include <cuda_runtime.h>
#include <cstdint>

// Problem constants
#define NROWS   524288          // NFRAG * FRAGLEN
#define DY      128
#define FRAG    1024
#define LEN     512
#define EPF     511             // edges per fragment
#define NEDGE   (FRAG * EPF)
#define DISTC   3.8f
#define NITERS  10
#define CONV    1e-4f
#define NB      9               // trials k=2..10 evaluated in k_iterB

// ---------------- device state (all reset / recomputed every launch) ----------------
__device__ float g_dx[NEDGE * 3];       // per-edge dx (first-3-coord diffs along chain)
__device__ float g_dA[NEDGE * 3];       // per-edge (lam3[n+1]-lam3[n]) @ A
__device__ float g_lam3[NROWS * 3];     // per-node lam3; holds r at init
__device__ float g_S3[NROWS * 3];       // sum of aeff_j * lam3_j  (applied lazily)
__device__ float g_pA[3 * FRAG];        // A partials: trial0, trial1, cnorm
__device__ float g_pB[NB * FRAG];       // B partials: trials k=2..10
__device__ float g_V[DY * 3];           // V[d][j] = Wu[d,j]+Wu[d,j+3]+Wu[d,j+6]
__device__ float g_A[9];                // A[j][i] = sum_d V[d][j] * Wp[i,d]
__device__ float g_alpha, g_aeff, g_Sa, g_cn;
__device__ int   g_done, g_decided;
__device__ unsigned g_cntA, g_cntB;

// ---------------- precompute V (128x3), A (3x3); reset all scalar state ----------------
__global__ void k_pre(const float* __restrict__ Wp, const float* __restrict__ Wu) {
    int d = threadIdx.x;  // 0..127
    if (d == 0) {
        g_alpha = 1.0f; g_aeff = 0.0f; g_Sa = 0.0f;
        g_done = 0; g_decided = 0; g_cntA = 0; g_cntB = 0;
    }
    float v[3];
#pragma unroll
    for (int j = 0; j < 3; j++) {
        v[j] = Wu[d * 18 + j] + Wu[d * 18 + j + 3] + Wu[d * 18 + j + 6];
        g_V[d * 3 + j] = v[j];
    }
    __shared__ float red[128];
#pragma unroll
    for (int j = 0; j < 3; j++) {
#pragma unroll
        for (int i = 0; i < 3; i++) {
            red[d] = v[j] * Wp[i * DY + d];
            __syncthreads();
            for (int s = 64; s > 0; s >>= 1) {
                if (d < s) red[d] += red[d + s];
                __syncthreads();
            }
            if (d == 0) g_A[j * 3 + i] = red[0];
            __syncthreads();
        }
    }
}

// ---------------- r[n] = y[n] @ Wp[0:3]^T  (bias cancels in diffs); zero S3 ----------------
__global__ void k_r(const float* __restrict__ y, const float* __restrict__ Wp) {
    int gid  = blockIdx.x * blockDim.x + threadIdx.x;
    int row  = gid >> 5;
    int lane = gid & 31;
    if (row >= NROWS) return;
    const float4 v = reinterpret_cast<const float4*>(y + (size_t)row * DY)[lane];
    int d = lane * 4;
    float p[3];
#pragma unroll
    for (int i = 0; i < 3; i++) {
        const float* w = Wp + i * DY + d;
        p[i] = v.x * w[0] + v.y * w[1] + v.z * w[2] + v.w * w[3];
    }
#pragma unroll
    for (int i = 0; i < 3; i++)
#pragma unroll
        for (int o = 16; o > 0; o >>= 1)
            p[i] += __shfl_down_sync(0xffffffffu, p[i], o);
    if (lane == 0) {
#pragma unroll
        for (int i = 0; i < 3; i++) {
            g_lam3[row * 3 + i] = p[i];   // r stored in lam3 buffer for iteration 0
            g_S3[row * 3 + i]   = 0.0f;
        }
    }
}

// ---------------- iteration kernel A: apply prev step, chain grad, trials k=0,1, decide ----------------
__global__ void __launch_bounds__(512) k_iterA(int j) {
    const int f = blockIdx.x;
    const int t = threadIdx.x;           // node index within fragment (0..511)

    if (g_done) {                        // converged: freeze everything
        if (f == 0 && t == 0) g_decided = 1;
        return;
    }

    const int n = f * LEN + t;
    const int e = f * EPF + t;           // edge index (valid for t < 511)

    __shared__ float ss[LEN * 3];
    __shared__ float wsum[16][3];
    __shared__ int slast;

    float dx0 = 0.f, dx1 = 0.f, dx2 = 0.f;

    if (j == 0) {
        float r0 = g_lam3[n * 3 + 0], r1 = g_lam3[n * 3 + 1], r2 = g_lam3[n * 3 + 2];
        ss[t * 3 + 0] = r0; ss[t * 3 + 1] = r1; ss[t * 3 + 2] = r2;
        __syncthreads();
        if (t < EPF) {
            dx0 = ss[(t + 1) * 3 + 0] - r0;
            dx1 = ss[(t + 1) * 3 + 1] - r1;
            dx2 = ss[(t + 1) * 3 + 2] - r2;
            g_dx[e * 3 + 0] = dx0; g_dx[e * 3 + 1] = dx1; g_dx[e * 3 + 2] = dx2;
        }
        __syncthreads();                 // before reusing ss for s
    } else {
        const float ae = g_aeff;
        if (t < EPF) {
            dx0 = g_dx[e * 3 + 0] - ae * g_dA[e * 3 + 0];
            dx1 = g_dx[e * 3 + 1] - ae * g_dA[e * 3 + 1];
            dx2 = g_dx[e * 3 + 2] - ae * g_dA[e * 3 + 2];
            g_dx[e * 3 + 0] = dx0; g_dx[e * 3 + 1] = dx1; g_dx[e * 3 + 2] = dx2;
        }
        // lazily fold previous step into S3 (g_lam3 still holds lam3_{j-1})
#pragma unroll
        for (int i = 0; i < 3; i++)
            g_S3[n * 3 + i] += ae * g_lam3[n * 3 + i];
    }

    // s[e] = DIST * drn2^{-1.5} * c * dx ;  c = DIST/|dx| - 1
    float c2 = 0.f;
    if (t < EPF) {
        float q  = dx0 * dx0 + dx1 * dx1 + dx2 * dx2;
        float rs = rsqrtf(q);
        float c  = fmaf(DISTC, rs, -1.0f);
        float coef = DISTC * rs * rs * rs * c;
        ss[t * 3 + 0] = coef * dx0;
        ss[t * 3 + 1] = coef * dx1;
        ss[t * 3 + 2] = coef * dx2;
        c2 = c * c;
    }
    __syncthreads();

    // lam3[n] = s[n] - s[n-1], boundaries s[-1] = s[L-1] = 0
    float l0, l1, l2;
    if (t == 0)       { l0 = ss[0]; l1 = ss[1]; l2 = ss[2]; }
    else if (t < EPF) { l0 = ss[t*3+0] - ss[(t-1)*3+0];
                        l1 = ss[t*3+1] - ss[(t-1)*3+1];
                        l2 = ss[t*3+2] - ss[(t-1)*3+2]; }
    else              { l0 = -ss[(EPF-1)*3+0]; l1 = -ss[(EPF-1)*3+1]; l2 = -ss[(EPF-1)*3+2]; }
    g_lam3[n * 3 + 0] = l0; g_lam3[n * 3 + 1] = l1; g_lam3[n * 3 + 2] = l2;

    float acc0 = 0.f, acc1 = 0.f;
    if (t < EPF) {
        // lam3[t+1]
        float m0, m1, m2;
        if (t + 1 < EPF) { m0 = ss[(t+1)*3+0] - ss[t*3+0];
                           m1 = ss[(t+1)*3+1] - ss[t*3+1];
                           m2 = ss[(t+1)*3+2] - ss[t*3+2]; }
        else             { m0 = -ss[(EPF-1)*3+0]; m1 = -ss[(EPF-1)*3+1]; m2 = -ss[(EPF-1)*3+2]; }
        float d0 = m0 - l0, d1 = m1 - l1, d2 = m2 - l2;
        float a0v = d0 * g_A[0] + d1 * g_A[3] + d2 * g_A[6];
        float a1v = d0 * g_A[1] + d1 * g_A[4] + d2 * g_A[7];
        float a2v = d0 * g_A[2] + d1 * g_A[5] + d2 * g_A[8];
        g_dA[e * 3 + 0] = a0v; g_dA[e * 3 + 1] = a1v; g_dA[e * 3 + 2] = a2v;

        float a = g_alpha;
#pragma unroll
        for (int k = 0; k < 2; k++) {
            float v0 = fmaf(-a, a0v, dx0);
            float v1 = fmaf(-a, a1v, dx1);
            float v2 = fmaf(-a, a2v, dx2);
            float q  = v0 * v0 + v1 * v1 + v2 * v2;
            float term = fmaf(DISTC, rsqrtf(q), -1.0f);
            if (k == 0) acc0 = term * term; else acc1 = term * term;
            a *= 0.5f;
        }
    }

    // deterministic block reduction of 3 values
    float vals[3] = {acc0, acc1, c2};
#pragma unroll
    for (int k = 0; k < 3; k++)
#pragma unroll
        for (int o = 16; o > 0; o >>= 1)
            vals[k] += __shfl_down_sync(0xffffffffu, vals[k], o);
    int lane = t & 31, w = t >> 5;
    if (lane == 0) { wsum[w][0] = vals[0]; wsum[w][1] = vals[1]; wsum[w][2] = vals[2]; }
    __syncthreads();
    if (t == 0) {
        float s0 = 0.f, s1 = 0.f, s2 = 0.f;
#pragma unroll
        for (int ww = 0; ww < 16; ww++) { s0 += wsum[ww][0]; s1 += wsum[ww][1]; s2 += wsum[ww][2]; }
        g_pA[0 * FRAG + f] = s0;
        g_pA[1 * FRAG + f] = s1;
        g_pA[2 * FRAG + f] = s2;
        __threadfence();
        slast = (atomicAdd(&g_cntA, 1u) == FRAG - 1);
    }
    __syncthreads();
    if (!slast) return;

    // ---- last block: grid reduce (fixed order -> deterministic) + decision ----
    float u[3];
#pragma unroll
    for (int k = 0; k < 3; k++) {
        u[k] = g_pA[k * FRAG + t] + g_pA[k * FRAG + t + 512];
#pragma unroll
        for (int o = 16; o > 0; o >>= 1)
            u[k] += __shfl_down_sync(0xffffffffu, u[k], o);
    }
    if (lane == 0) { wsum[w][0] = u[0]; wsum[w][1] = u[1]; wsum[w][2] = u[2]; }
    __syncthreads();
    if (t == 0) {
        float tot0 = 0.f, tot1 = 0.f, cn = 0.f;
#pragma unroll
        for (int ww = 0; ww < 16; ww++) { tot0 += wsum[ww][0]; tot1 += wsum[ww][1]; cn += wsum[ww][2]; }
        g_cntA = 0;
        float a0 = g_alpha;
        if (tot0 < cn) {                       // accept at ls=0 (1.5x boost rule applies)
            float af = a0, ctry = tot0;
            if (ctry > CONV) af *= 1.5f;
            g_alpha = af; g_aeff = af; g_Sa += af;
            if (ctry < CONV) g_done = 1;
            g_decided = 1;
        } else if (tot1 < cn) {                // accept at ls=1
            float af = a0 * 0.5f, ctry = tot1;
            g_alpha = af; g_aeff = af; g_Sa += af;
            if (ctry < CONV) g_done = 1;
            g_decided = 1;
        } else {                               // defer to k_iterB
            g_decided = 0; g_cn = cn;
        }
    }
}

// ---------------- iteration kernel B: trials k=2..10 (runs only if A undecided) ----------------
__global__ void __launch_bounds__(512) k_iterB() {
    if (g_decided) return;
    const int f = blockIdx.x;
    const int t = threadIdx.x;
    const int e = f * EPF + t;

    __shared__ float wsum[16][NB];
    __shared__ int slast;

    float acc[NB];
#pragma unroll
    for (int i = 0; i < NB; i++) acc[i] = 0.f;

    if (t < EPF) {
        float dx0 = g_dx[e * 3 + 0], dx1 = g_dx[e * 3 + 1], dx2 = g_dx[e * 3 + 2];
        float a0v = g_dA[e * 3 + 0], a1v = g_dA[e * 3 + 1], a2v = g_dA[e * 3 + 2];
        float a = g_alpha * 0.25f;             // k=2
#pragma unroll
        for (int i = 0; i < NB; i++) {
            float v0 = fmaf(-a, a0v, dx0);
            float v1 = fmaf(-a, a1v, dx1);
            float v2 = fmaf(-a, a2v, dx2);
            float q  = v0 * v0 + v1 * v1 + v2 * v2;
            float term = fmaf(DISTC, rsqrtf(q), -1.0f);
            acc[i] = term * term;
            a *= 0.5f;
        }
    }

#pragma unroll
    for (int i = 0; i < NB; i++)
#pragma unroll
        for (int o = 16; o > 0; o >>= 1)
            acc[i] += __shfl_down_sync(0xffffffffu, acc[i], o);
    int lane = t & 31, w = t >> 5;
    if (lane == 0)
#pragma unroll
        for (int i = 0; i < NB; i++) wsum[w][i] = acc[i];
    __syncthreads();
    if (t == 0) {
#pragma unroll
        for (int i = 0; i < NB; i++) {
            float s = 0.f;
#pragma unroll
            for (int ww = 0; ww < 16; ww++) s += wsum[ww][i];
            g_pB[i * FRAG + f] = s;
        }
        __threadfence();
        slast = (atomicAdd(&g_cntB, 1u) == FRAG - 1);
    }
    __syncthreads();
    if (!slast) return;

    float u[NB];
#pragma unroll
    for (int i = 0; i < NB; i++) {
        u[i] = g_pB[i * FRAG + t] + g_pB[i * FRAG + t + 512];
#pragma unroll
        for (int o = 16; o > 0; o >>= 1)
            u[i] += __shfl_down_sync(0xffffffffu, u[i], o);
    }
    if (lane == 0)
#pragma unroll
        for (int i = 0; i < NB; i++) wsum[w][i] = u[i];
    __syncthreads();
    if (t == 0) {
        float tot[NB];
#pragma unroll
        for (int i = 0; i < NB; i++) {
            float s = 0.f;
#pragma unroll
            for (int ww = 0; ww < 16; ww++) s += wsum[ww][i];
            tot[i] = s;
        }
        g_cntB = 0;
        float a0 = g_alpha, cn = g_cn;
        int kf = -1;
#pragma unroll
        for (int i = 0; i < NB; i++)
            if (kf < 0 && tot[i] < cn) kf = i;
        float af, ctry;
        if (kf >= 0) { af = ldexpf(a0, -(kf + 2)); ctry = tot[kf]; }
        else         { af = ldexpf(a0, -11); ctry = tot[NB - 1]; }   // all fail: ls=11
        g_alpha = af; g_aeff = af; g_Sa += af;
        if (ctry < CONV) g_done = 1;
    }
}

// ---------------- y_out = y0 - (S3 + a_last*lam3) @ V^T - Sa * b_u ----------------
__global__ void k_final(const float* __restrict__ y, const float* __restrict__ bu,
                        float* __restrict__ out) {
    int gid  = blockIdx.x * blockDim.x + threadIdx.x;
    int row  = gid >> 5;
    int lane = gid & 31;
    if (row >= NROWS) return;
    const float ae = g_aeff, Sa = g_Sa;
    float s0 = g_S3[row * 3 + 0] + ae * g_lam3[row * 3 + 0];
    float s1 = g_S3[row * 3 + 1] + ae * g_lam3[row * 3 + 1];
    float s2 = g_S3[row * 3 + 2] + ae * g_lam3[row * 3 + 2];
    int d = lane * 4;
    float4 yv = reinterpret_cast<const float4*>(y + (size_t)row * DY)[lane];
    float4 bv = reinterpret_cast<const float4*>(bu)[lane];
    float4 o;
    o.x = yv.x - (s0 * g_V[(d+0)*3+0] + s1 * g_V[(d+0)*3+1] + s2 * g_V[(d+0)*3+2]) - Sa * bv.x;
    o.y = yv.y - (s0 * g_V[(d+1)*3+0] + s1 * g_V[(d+1)*3+1] + s2 * g_V[(d+1)*3+2]) - Sa * bv.y;
    o.z = yv.z - (s0 * g_V[(d+2)*3+0] + s1 * g_V[(d+2)*3+1] + s2 * g_V[(d+2)*3+2]) - Sa * bv.z;
    o.w = yv.w - (s0 * g_V[(d+3)*3+0] + s1 * g_V[(d+3)*3+1] + s2 * g_V[(d+3)*3+2]) - Sa * bv.w;
    reinterpret_cast<float4*>(out + (size_t)row * DY)[lane] = o;
}

extern "C" void kernel_launch(void* const* d_in, const int* in_sizes, int n_in,
                              void* d_out, int out_size) {
    const float* y  = (const float*)d_in[0];
    const float* Wp = (const float*)d_in[1];
    // d_in[2] = b_p (cancels in edge diffs), d_in[5]=batch, d_in[6]=fragid (baked in)
    const float* Wu = (const float*)d_in[3];
    const float* bu = (const float*)d_in[4];
    float* out = (float*)d_out;

    k_pre<<<1, 128>>>(Wp, Wu);
    k_r<<<NROWS / 8, 256>>>(y, Wp);
    for (int j = 0; j < NITERS; j++) {
        k_iterA<<<FRAG, 512>>>(j);
        k_iterB<<<FRAG, 512>>>();
    }
    k_final<<<NROWS / 8, 256>>>(y, bu, out);
}